// round 3
// baseline (speedup 1.0000x reference)
#include <cuda_runtime.h>
#include <math.h>

#define NB 1024
#define TE 168
#define TD 24
#define NF 64
#define NH 128

__device__ float g_mid[NB * TE * NH];
__device__ float g_wx [NB * TE * NH];
__device__ float g_hm [NB * NH];
__device__ float g_cm [NB * NH];

__device__ __forceinline__ float sigm(float x) { return 1.0f / (1.0f + expf(-x)); }

__device__ __forceinline__ void fma4(float& acc, const float4 a, const float4 b) {
    acc = fmaf(a.x, b.x, fmaf(a.y, b.y, fmaf(a.z, b.z, fmaf(a.w, b.w, acc))));
}

// ---------------- Kernel 1: encoder (attention LSTM) + mid LSTM ----------------
__global__ __launch_bounds__(256, 1)
void k_enc_mid(const float* __restrict__ X,
               const float* __restrict__ Wi_w, const float* __restrict__ Wi_b,
               const float* __restrict__ We_w,
               const float* __restrict__ Vd_w, const float* __restrict__ Vd_b,
               const float* __restrict__ eWih, const float* __restrict__ eWhh,
               const float* __restrict__ ebih, const float* __restrict__ ebhh,
               const float* __restrict__ mWih, const float* __restrict__ mWhh,
               const float* __restrict__ mbih, const float* __restrict__ mbhh)
{
    __shared__ __align__(16) float hc [8][256];   // enc [h|c]
    __shared__ __align__(16) float hmc[8][256];   // mid [h|c]
    __shared__ __align__(16) float xt [8][64];
    __shared__ __align__(16) float t1s[8][128];
    __shared__ __align__(16) float ssm[8][64];
    __shared__ __align__(16) float xin[8][64];
    __shared__ __align__(16) float gsm[8][512];

    const int tid = threadIdx.x;
    const int r0  = blockIdx.x * 8;

    for (int i = tid; i < 8 * 256; i += 256) {
        hc[i >> 8][i & 255] = 0.0f;
        hmc[i >> 8][i & 255] = 0.0f;
    }
    __syncthreads();

    for (int t = 0; t < TE; ++t) {
        for (int i = tid; i < 8 * 64; i += 256)
            xt[i >> 6][i & 63] = X[((r0 + (i >> 6)) * TE + t) * NF + (i & 63)];
        __syncthreads();

        // t1 = tanh([h,c]@We^T + x@Wi^T + Wi_b)   [8 rows x 128]
        {
            const int j = tid & 127, rb = (tid >> 7) * 4;
            float a0 = Wi_b[j], a1 = a0, a2 = a0, a3 = a0;
            const float4* w4 = (const float4*)(We_w + j * 256);
            const float4* p0 = (const float4*)hc[rb + 0];
            const float4* p1 = (const float4*)hc[rb + 1];
            const float4* p2 = (const float4*)hc[rb + 2];
            const float4* p3 = (const float4*)hc[rb + 3];
            #pragma unroll 8
            for (int k = 0; k < 64; ++k) {
                const float4 w = w4[k];
                fma4(a0, w, p0[k]);
                fma4(a1, w, p1[k]);
                fma4(a2, w, p2[k]);
                fma4(a3, w, p3[k]);
            }
            const float4* wi4 = (const float4*)(Wi_w + j * 64);
            const float4* q0 = (const float4*)xt[rb + 0];
            const float4* q1 = (const float4*)xt[rb + 1];
            const float4* q2 = (const float4*)xt[rb + 2];
            const float4* q3 = (const float4*)xt[rb + 3];
            #pragma unroll
            for (int k = 0; k < 16; ++k) {
                const float4 w = wi4[k];
                fma4(a0, w, q0[k]);
                fma4(a1, w, q1[k]);
                fma4(a2, w, q2[k]);
                fma4(a3, w, q3[k]);
            }
            t1s[rb + 0][j] = tanhf(a0);
            t1s[rb + 1][j] = tanhf(a1);
            t1s[rb + 2][j] = tanhf(a2);
            t1s[rb + 3][j] = tanhf(a3);
        }
        __syncthreads();

        // s = t1 @ Vd^T + Vd_b   [8 x 64]
        {
            const int f = tid & 63, ra = (tid >> 6) * 2;
            float a0 = Vd_b[f], a1 = a0;
            const float4* w4 = (const float4*)(Vd_w + f * 128);
            const float4* p0 = (const float4*)t1s[ra];
            const float4* p1 = (const float4*)t1s[ra + 1];
            #pragma unroll 8
            for (int k = 0; k < 32; ++k) {
                const float4 w = w4[k];
                fma4(a0, w, p0[k]);
                fma4(a1, w, p1[k]);
            }
            ssm[ra][f] = a0; ssm[ra + 1][f] = a1;
        }
        __syncthreads();

        // x_in = x * softmax(s)  (one warp per row)
        {
            const int w = tid >> 5, lane = tid & 31;
            float v0 = ssm[w][lane], v1 = ssm[w][lane + 32];
            float mx = fmaxf(v0, v1);
            #pragma unroll
            for (int o = 16; o; o >>= 1) mx = fmaxf(mx, __shfl_xor_sync(~0u, mx, o));
            float e0 = expf(v0 - mx), e1 = expf(v1 - mx);
            float sm = e0 + e1;
            #pragma unroll
            for (int o = 16; o; o >>= 1) sm += __shfl_xor_sync(~0u, sm, o);
            float inv = 1.0f / sm;
            xin[w][lane]      = xt[w][lane]      * e0 * inv;
            xin[w][lane + 32] = xt[w][lane + 32] * e1 * inv;
        }
        __syncthreads();

        // enc gates: g = x_in@eWih^T + h@eWhh^T + b   [8 x 512]
        {
            const int c0 = tid, c1 = tid + 256;
            float A0[8], A1[8];
            const float b0 = ebih[c0] + ebhh[c0], b1 = ebih[c1] + ebhh[c1];
            #pragma unroll
            for (int r = 0; r < 8; ++r) { A0[r] = b0; A1[r] = b1; }
            const float4* wa = (const float4*)(eWih + c0 * 64);
            const float4* wb = (const float4*)(eWih + c1 * 64);
            #pragma unroll 4
            for (int k = 0; k < 16; ++k) {
                const float4 u = wa[k], w = wb[k];
                #pragma unroll
                for (int r = 0; r < 8; ++r) {
                    const float4 v = ((const float4*)xin[r])[k];
                    fma4(A0[r], u, v); fma4(A1[r], w, v);
                }
            }
            const float4* ha = (const float4*)(eWhh + c0 * 128);
            const float4* hb = (const float4*)(eWhh + c1 * 128);
            #pragma unroll 2
            for (int k = 0; k < 32; ++k) {
                const float4 u = ha[k], w = hb[k];
                #pragma unroll
                for (int r = 0; r < 8; ++r) {
                    const float4 v = ((const float4*)hc[r])[k];
                    fma4(A0[r], u, v); fma4(A1[r], w, v);
                }
            }
            #pragma unroll
            for (int r = 0; r < 8; ++r) { gsm[r][c0] = A0[r]; gsm[r][c1] = A1[r]; }
        }
        __syncthreads();

        // enc LSTM update
        for (int m = tid; m < 8 * 128; m += 256) {
            const int r = m >> 7, j = m & 127;
            const float c = sigm(gsm[r][j + 128]) * hc[r][128 + j]
                          + sigm(gsm[r][j]) * tanhf(gsm[r][j + 256]);
            hc[r][j]       = sigm(gsm[r][j + 384]) * tanhf(c);
            hc[r][128 + j] = c;
        }
        __syncthreads();

        // mid gates: g = h@mWih^T + hm@mWhh^T + b
        {
            const int c0 = tid, c1 = tid + 256;
            float A0[8], A1[8];
            const float b0 = mbih[c0] + mbhh[c0], b1 = mbih[c1] + mbhh[c1];
            #pragma unroll
            for (int r = 0; r < 8; ++r) { A0[r] = b0; A1[r] = b1; }
            const float4* wa = (const float4*)(mWih + c0 * 128);
            const float4* wb = (const float4*)(mWih + c1 * 128);
            #pragma unroll 2
            for (int k = 0; k < 32; ++k) {
                const float4 u = wa[k], w = wb[k];
                #pragma unroll
                for (int r = 0; r < 8; ++r) {
                    const float4 v = ((const float4*)hc[r])[k];
                    fma4(A0[r], u, v); fma4(A1[r], w, v);
                }
            }
            const float4* ha = (const float4*)(mWhh + c0 * 128);
            const float4* hb = (const float4*)(mWhh + c1 * 128);
            #pragma unroll 2
            for (int k = 0; k < 32; ++k) {
                const float4 u = ha[k], w = hb[k];
                #pragma unroll
                for (int r = 0; r < 8; ++r) {
                    const float4 v = ((const float4*)hmc[r])[k];
                    fma4(A0[r], u, v); fma4(A1[r], w, v);
                }
            }
            #pragma unroll
            for (int r = 0; r < 8; ++r) { gsm[r][c0] = A0[r]; gsm[r][c1] = A1[r]; }
        }
        __syncthreads();

        // mid LSTM update + store mid_out
        for (int m = tid; m < 8 * 128; m += 256) {
            const int r = m >> 7, j = m & 127;
            const float c = sigm(gsm[r][j + 128]) * hmc[r][128 + j]
                          + sigm(gsm[r][j]) * tanhf(gsm[r][j + 256]);
            const float h = sigm(gsm[r][j + 384]) * tanhf(c);
            hmc[r][j] = h; hmc[r][128 + j] = c;
            g_mid[((r0 + r) * TE + t) * NH + j] = h;
        }
        __syncthreads();
    }

    for (int i = tid; i < 8 * 128; i += 256) {
        const int r = i >> 7, j = i & 127;
        g_hm[(r0 + r) * NH + j] = hmc[r][j];
        g_cm[(r0 + r) * NH + j] = hmc[r][128 + j];
    }
}

// ---------------- Kernel 2: wx_mid = mid_out @ Wx^T + Wx_b ----------------
__global__ __launch_bounds__(256, 1)
void k_wx(const float* __restrict__ Wx_w, const float* __restrict__ Wx_b)
{
    __shared__ __align__(16) float ms[32][128];
    const int tid  = threadIdx.x;
    const int base = blockIdx.x * 32 * NH;

    for (int i = tid; i < 32 * 128; i += 256)
        ms[i >> 7][i & 127] = g_mid[base + i];
    __syncthreads();

    const int j = tid & 127, rg = tid >> 7;
    float acc[16];
    const float b = Wx_b[j];
    #pragma unroll
    for (int r = 0; r < 16; ++r) acc[r] = b;
    const float4* w4 = (const float4*)(Wx_w + j * 128);
    #pragma unroll 2
    for (int k = 0; k < 32; ++k) {
        const float4 w = w4[k];
        #pragma unroll
        for (int r = 0; r < 16; ++r) {
            const float4 v = ((const float4*)ms[rg * 16 + r])[k];
            fma4(acc[r], w, v);
        }
    }
    #pragma unroll
    for (int r = 0; r < 16; ++r)
        g_wx[base + (rg * 16 + r) * NH + j] = acc[r];
}

// ---------------- Kernel 3: temporal-attention decoder + head ----------------
__global__ __launch_bounds__(256, 1)
void k_dec(const float* __restrict__ Wh_w,
           const float* __restrict__ V_w,  const float* __restrict__ V_b,
           const float* __restrict__ dWih, const float* __restrict__ dWhh,
           const float* __restrict__ dbih, const float* __restrict__ dbhh,
           const float* __restrict__ regw, const float* __restrict__ regb,
           float* __restrict__ out)
{
    __shared__ __align__(16) float hic[8][256];
    __shared__ __align__(16) float qs [8][128];
    __shared__             float ss [8][TE];
    __shared__ __align__(16) float din[8][128];
    __shared__ __align__(16) float gsm[8][512];

    const int tid = threadIdx.x;
    const int r0  = blockIdx.x * 8;

    for (int i = tid; i < 8 * 256; i += 256) {
        const int r = i >> 8, k = i & 255;
        hic[r][k] = (k < 128) ? g_hm[(r0 + r) * NH + k]
                              : g_cm[(r0 + r) * NH + (k - 128)];
    }
    __syncthreads();

    for (int td = 0; td < TD; ++td) {
        // q = [hi,ci] @ Wh^T
        {
            const int j = tid & 127, rb = (tid >> 7) * 4;
            float a0 = 0.f, a1 = 0.f, a2 = 0.f, a3 = 0.f;
            const float4* w4 = (const float4*)(Wh_w + j * 256);
            const float4* p0 = (const float4*)hic[rb + 0];
            const float4* p1 = (const float4*)hic[rb + 1];
            const float4* p2 = (const float4*)hic[rb + 2];
            const float4* p3 = (const float4*)hic[rb + 3];
            #pragma unroll 8
            for (int k = 0; k < 64; ++k) {
                const float4 w = w4[k];
                fma4(a0, w, p0[k]);
                fma4(a1, w, p1[k]);
                fma4(a2, w, p2[k]);
                fma4(a3, w, p3[k]);
            }
            qs[rb + 0][j] = a0; qs[rb + 1][j] = a1;
            qs[rb + 2][j] = a2; qs[rb + 3][j] = a3;
        }
        __syncthreads();

        // scores: ss[r][t] = tanh(q + wx[t]) . V_w + V_b
        for (int id = tid; id < 8 * TE; id += 256) {
            const int r = id / TE, tt = id % TE;
            const float4* x4 = (const float4*)(g_wx + ((r0 + r) * TE + tt) * NH);
            const float4* q4 = (const float4*)qs[r];
            const float4* v4 = (const float4*)V_w;
            float acc = V_b[0];
            #pragma unroll 4
            for (int k = 0; k < 32; ++k) {
                const float4 q = q4[k], x = x4[k], v = v4[k];
                acc = fmaf(tanhf(q.x + x.x), v.x, acc);
                acc = fmaf(tanhf(q.y + x.y), v.y, acc);
                acc = fmaf(tanhf(q.z + x.z), v.z, acc);
                acc = fmaf(tanhf(q.w + x.w), v.w, acc);
            }
            ss[r][tt] = acc;
        }
        __syncthreads();

        // dec_in[j] = sum_t ss[t] * mid[t][j]
        {
            const int j = tid & 127, rb = (tid >> 7) * 4;
            float a0 = 0.f, a1 = 0.f, a2 = 0.f, a3 = 0.f;
            const float* m0 = g_mid + (r0 + rb + 0) * TE * NH + j;
            const float* m1 = g_mid + (r0 + rb + 1) * TE * NH + j;
            const float* m2 = g_mid + (r0 + rb + 2) * TE * NH + j;
            const float* m3 = g_mid + (r0 + rb + 3) * TE * NH + j;
            for (int tt = 0; tt < TE; ++tt) {
                a0 = fmaf(ss[rb + 0][tt], m0[tt * NH], a0);
                a1 = fmaf(ss[rb + 1][tt], m1[tt * NH], a1);
                a2 = fmaf(ss[rb + 2][tt], m2[tt * NH], a2);
                a3 = fmaf(ss[rb + 3][tt], m3[tt * NH], a3);
            }
            din[rb + 0][j] = a0; din[rb + 1][j] = a1;
            din[rb + 2][j] = a2; din[rb + 3][j] = a3;
        }
        __syncthreads();

        // dec gates
        {
            const int c0 = tid, c1 = tid + 256;
            float A0[8], A1[8];
            const float b0 = dbih[c0] + dbhh[c0], b1 = dbih[c1] + dbhh[c1];
            #pragma unroll
            for (int r = 0; r < 8; ++r) { A0[r] = b0; A1[r] = b1; }
            const float4* wa = (const float4*)(dWih + c0 * 128);
            const float4* wb = (const float4*)(dWih + c1 * 128);
            #pragma unroll 2
            for (int k = 0; k < 32; ++k) {
                const float4 u = wa[k], w = wb[k];
                #pragma unroll
                for (int r = 0; r < 8; ++r) {
                    const float4 v = ((const float4*)din[r])[k];
                    fma4(A0[r], u, v); fma4(A1[r], w, v);
                }
            }
            const float4* ha = (const float4*)(dWhh + c0 * 128);
            const float4* hb = (const float4*)(dWhh + c1 * 128);
            #pragma unroll 2
            for (int k = 0; k < 32; ++k) {
                const float4 u = ha[k], w = hb[k];
                #pragma unroll
                for (int r = 0; r < 8; ++r) {
                    const float4 v = ((const float4*)hic[r])[k];
                    fma4(A0[r], u, v); fma4(A1[r], w, v);
                }
            }
            #pragma unroll
            for (int r = 0; r < 8; ++r) { gsm[r][c0] = A0[r]; gsm[r][c1] = A1[r]; }
        }
        __syncthreads();

        // dec LSTM update
        for (int m = tid; m < 8 * 128; m += 256) {
            const int r = m >> 7, j = m & 127;
            const float c = sigm(gsm[r][j + 128]) * hic[r][128 + j]
                          + sigm(gsm[r][j]) * tanhf(gsm[r][j + 256]);
            hic[r][j]       = sigm(gsm[r][j + 384]) * tanhf(c);
            hic[r][128 + j] = c;
        }
        __syncthreads();

        // out[b, td] = hi . reg_w + reg_b
        {
            const int w = tid >> 5, lane = tid & 31;
            float acc =            hic[w][lane]      * regw[lane];
            acc = fmaf(hic[w][lane + 32], regw[lane + 32], acc);
            acc = fmaf(hic[w][lane + 64], regw[lane + 64], acc);
            acc = fmaf(hic[w][lane + 96], regw[lane + 96], acc);
            #pragma unroll
            for (int o = 16; o; o >>= 1) acc += __shfl_xor_sync(~0u, acc, o);
            if (lane == 0) out[(r0 + w) * TD + td] = acc + regb[0];
        }
        __syncthreads();
    }
}

extern "C" void kernel_launch(void* const* d_in, const int* in_sizes, int n_in,
                              void* d_out, int out_size)
{
    const float* X    = (const float*)d_in[0];
    const float* Wi_w = (const float*)d_in[2];
    const float* Wi_b = (const float*)d_in[3];
    const float* We_w = (const float*)d_in[4];
    const float* Vd_w = (const float*)d_in[5];
    const float* Vd_b = (const float*)d_in[6];
    const float* eWih = (const float*)d_in[7];
    const float* eWhh = (const float*)d_in[8];
    const float* ebih = (const float*)d_in[9];
    const float* ebhh = (const float*)d_in[10];
    const float* mWih = (const float*)d_in[11];
    const float* mWhh = (const float*)d_in[12];
    const float* mbih = (const float*)d_in[13];
    const float* mbhh = (const float*)d_in[14];
    const float* Wx_w = (const float*)d_in[15];
    const float* Wx_b = (const float*)d_in[16];
    const float* Wh_w = (const float*)d_in[17];
    const float* V_w  = (const float*)d_in[18];
    const float* V_b  = (const float*)d_in[19];
    const float* dWih = (const float*)d_in[20];
    const float* dWhh = (const float*)d_in[21];
    const float* dbih = (const float*)d_in[22];
    const float* dbhh = (const float*)d_in[23];
    const float* regw = (const float*)d_in[24];
    const float* regb = (const float*)d_in[25];

    k_enc_mid<<<NB / 8, 256>>>(X, Wi_w, Wi_b, We_w, Vd_w, Vd_b,
                               eWih, eWhh, ebih, ebhh,
                               mWih, mWhh, mbih, mbhh);
    k_wx<<<(NB * TE) / 32, 256>>>(Wx_w, Wx_b);
    k_dec<<<NB / 8, 256>>>(Wh_w, V_w, V_b, dWih, dWhh, dbih, dbhh,
                           regw, regb, (float*)d_out);
}

// round 5
// speedup vs baseline: 1.2275x; 1.2275x over previous
#include <cuda_runtime.h>
#include <math.h>

#define NB 1024
#define TE 168
#define TD 24
#define NF 64
#define NH 128

__device__ float g_mid[NB * TE * NH];
__device__ float g_wx [NB * TE * NH];
__device__ float g_hm [NB * NH];
__device__ float g_cm [NB * NH];

// transposed (k-major) weights
__device__ float gT_eWih[64 * 512];
__device__ float gT_eWhh[128 * 512];
__device__ float gT_mWih[128 * 512];
__device__ float gT_mWhh[128 * 512];
__device__ float gT_dWih[128 * 512];
__device__ float gT_dWhh[128 * 512];
__device__ float gT_We [256 * 128];
__device__ float gT_Wi [64 * 128];
__device__ float gT_Vd [128 * 64];
__device__ float gT_Wh [256 * 128];
__device__ float gT_Wx [128 * 128];

__device__ __forceinline__ float sigm(float x) { return 1.0f / (1.0f + expf(-x)); }

// ---------------- Kernel 0: transpose weights to k-major ----------------
__global__ void k_tr(const float* __restrict__ eWih, const float* __restrict__ eWhh,
                     const float* __restrict__ mWih, const float* __restrict__ mWhh,
                     const float* __restrict__ dWih, const float* __restrict__ dWhh,
                     const float* __restrict__ We,   const float* __restrict__ Wi,
                     const float* __restrict__ Vd,   const float* __restrict__ Wh,
                     const float* __restrict__ Wx)
{
    const int i0 = blockIdx.x * blockDim.x + threadIdx.x;
    const int st = gridDim.x * blockDim.x;
    for (int i = i0; i < 512 * 64;  i += st) gT_eWih[(i % 64)  * 512 + i / 64 ] = eWih[i];
    for (int i = i0; i < 512 * 128; i += st) gT_eWhh[(i % 128) * 512 + i / 128] = eWhh[i];
    for (int i = i0; i < 512 * 128; i += st) gT_mWih[(i % 128) * 512 + i / 128] = mWih[i];
    for (int i = i0; i < 512 * 128; i += st) gT_mWhh[(i % 128) * 512 + i / 128] = mWhh[i];
    for (int i = i0; i < 512 * 128; i += st) gT_dWih[(i % 128) * 512 + i / 128] = dWih[i];
    for (int i = i0; i < 512 * 128; i += st) gT_dWhh[(i % 128) * 512 + i / 128] = dWhh[i];
    for (int i = i0; i < 128 * 256; i += st) gT_We [(i % 256) * 128 + i / 256] = We[i];
    for (int i = i0; i < 128 * 64;  i += st) gT_Wi [(i % 64)  * 128 + i / 64 ] = Wi[i];
    for (int i = i0; i < 64 * 128;  i += st) gT_Vd [(i % 128) * 64  + i / 128] = Vd[i];
    for (int i = i0; i < 128 * 256; i += st) gT_Wh [(i % 256) * 128 + i / 256] = Wh[i];
    for (int i = i0; i < 128 * 128; i += st) gT_Wx [(i % 128) * 128 + i / 128] = Wx[i];
}

// ---------------- Kernel 1: encoder (attention LSTM) + mid LSTM ----------------
__global__ __launch_bounds__(256, 1)
void k_enc_mid(const float* __restrict__ X,
               const float* __restrict__ Wi_b, const float* __restrict__ Vd_b,
               const float* __restrict__ ebih, const float* __restrict__ ebhh,
               const float* __restrict__ mbih, const float* __restrict__ mbhh)
{
    __shared__ __align__(16) float hc [8][256];   // enc [h|c]
    __shared__ __align__(16) float hmc[8][256];   // mid [h|c]
    __shared__ __align__(16) float xt [8][64];
    __shared__ __align__(16) float t1s[8][128];
    __shared__ __align__(16) float ssm[8][64];
    __shared__ __align__(16) float xin[8][64];
    __shared__ __align__(16) float gsm[8][512];

    const int tid = threadIdx.x;
    const int r0  = blockIdx.x * 8;

    for (int i = tid; i < 8 * 256; i += 256) {
        hc[i >> 8][i & 255] = 0.0f;
        hmc[i >> 8][i & 255] = 0.0f;
    }
    __syncthreads();

    for (int t = 0; t < TE; ++t) {
        for (int i = tid; i < 8 * 64; i += 256)
            xt[i >> 6][i & 63] = X[((r0 + (i >> 6)) * TE + t) * NF + (i & 63)];
        __syncthreads();

        // t1 = tanh([h,c]@We^T + x@Wi^T + Wi_b)   [8 rows x 128]
        {
            const int j = tid & 127, rb = (tid >> 7) * 4;
            float a0 = Wi_b[j], a1 = a0, a2 = a0, a3 = a0;
            #pragma unroll 4
            for (int k = 0; k < 256; k += 4) {
                const float w0 = gT_We[(k + 0) * 128 + j];
                const float w1 = gT_We[(k + 1) * 128 + j];
                const float w2 = gT_We[(k + 2) * 128 + j];
                const float w3 = gT_We[(k + 3) * 128 + j];
                float4 v;
                v = ((const float4*)hc[rb + 0])[k >> 2];
                a0 = fmaf(w0, v.x, fmaf(w1, v.y, fmaf(w2, v.z, fmaf(w3, v.w, a0))));
                v = ((const float4*)hc[rb + 1])[k >> 2];
                a1 = fmaf(w0, v.x, fmaf(w1, v.y, fmaf(w2, v.z, fmaf(w3, v.w, a1))));
                v = ((const float4*)hc[rb + 2])[k >> 2];
                a2 = fmaf(w0, v.x, fmaf(w1, v.y, fmaf(w2, v.z, fmaf(w3, v.w, a2))));
                v = ((const float4*)hc[rb + 3])[k >> 2];
                a3 = fmaf(w0, v.x, fmaf(w1, v.y, fmaf(w2, v.z, fmaf(w3, v.w, a3))));
            }
            #pragma unroll 4
            for (int k = 0; k < 64; k += 4) {
                const float w0 = gT_Wi[(k + 0) * 128 + j];
                const float w1 = gT_Wi[(k + 1) * 128 + j];
                const float w2 = gT_Wi[(k + 2) * 128 + j];
                const float w3 = gT_Wi[(k + 3) * 128 + j];
                float4 v;
                v = ((const float4*)xt[rb + 0])[k >> 2];
                a0 = fmaf(w0, v.x, fmaf(w1, v.y, fmaf(w2, v.z, fmaf(w3, v.w, a0))));
                v = ((const float4*)xt[rb + 1])[k >> 2];
                a1 = fmaf(w0, v.x, fmaf(w1, v.y, fmaf(w2, v.z, fmaf(w3, v.w, a1))));
                v = ((const float4*)xt[rb + 2])[k >> 2];
                a2 = fmaf(w0, v.x, fmaf(w1, v.y, fmaf(w2, v.z, fmaf(w3, v.w, a2))));
                v = ((const float4*)xt[rb + 3])[k >> 2];
                a3 = fmaf(w0, v.x, fmaf(w1, v.y, fmaf(w2, v.z, fmaf(w3, v.w, a3))));
            }
            t1s[rb + 0][j] = tanhf(a0);
            t1s[rb + 1][j] = tanhf(a1);
            t1s[rb + 2][j] = tanhf(a2);
            t1s[rb + 3][j] = tanhf(a3);
        }
        __syncthreads();

        // s = t1 @ Vd^T + Vd_b   [8 x 64]
        {
            const int f = tid & 63, ra = (tid >> 6) * 2;
            float a0 = Vd_b[f], a1 = a0;
            #pragma unroll 4
            for (int k = 0; k < 128; k += 4) {
                const float w0 = gT_Vd[(k + 0) * 64 + f];
                const float w1 = gT_Vd[(k + 1) * 64 + f];
                const float w2 = gT_Vd[(k + 2) * 64 + f];
                const float w3 = gT_Vd[(k + 3) * 64 + f];
                float4 v;
                v = ((const float4*)t1s[ra])[k >> 2];
                a0 = fmaf(w0, v.x, fmaf(w1, v.y, fmaf(w2, v.z, fmaf(w3, v.w, a0))));
                v = ((const float4*)t1s[ra + 1])[k >> 2];
                a1 = fmaf(w0, v.x, fmaf(w1, v.y, fmaf(w2, v.z, fmaf(w3, v.w, a1))));
            }
            ssm[ra][f] = a0; ssm[ra + 1][f] = a1;
        }
        __syncthreads();

        // x_in = x * softmax(s)  (one warp per row)
        {
            const int w = tid >> 5, lane = tid & 31;
            float v0 = ssm[w][lane], v1 = ssm[w][lane + 32];
            float mx = fmaxf(v0, v1);
            #pragma unroll
            for (int o = 16; o; o >>= 1) mx = fmaxf(mx, __shfl_xor_sync(~0u, mx, o));
            float e0 = expf(v0 - mx), e1 = expf(v1 - mx);
            float sm = e0 + e1;
            #pragma unroll
            for (int o = 16; o; o >>= 1) sm += __shfl_xor_sync(~0u, sm, o);
            float inv = 1.0f / sm;
            xin[w][lane]      = xt[w][lane]      * e0 * inv;
            xin[w][lane + 32] = xt[w][lane + 32] * e1 * inv;
        }
        __syncthreads();

        // enc gates: g = x_in@eWih^T + h@eWhh^T + b   [8 x 512]
        {
            const int c0 = tid, c1 = tid + 256;
            float A0[8], A1[8];
            const float b0 = ebih[c0] + ebhh[c0], b1 = ebih[c1] + ebhh[c1];
            #pragma unroll
            for (int r = 0; r < 8; ++r) { A0[r] = b0; A1[r] = b1; }
            #pragma unroll 2
            for (int k = 0; k < 64; k += 4) {
                const float u0 = gT_eWih[(k + 0) * 512 + c0];
                const float u1 = gT_eWih[(k + 1) * 512 + c0];
                const float u2 = gT_eWih[(k + 2) * 512 + c0];
                const float u3 = gT_eWih[(k + 3) * 512 + c0];
                const float w0 = gT_eWih[(k + 0) * 512 + c1];
                const float w1 = gT_eWih[(k + 1) * 512 + c1];
                const float w2 = gT_eWih[(k + 2) * 512 + c1];
                const float w3 = gT_eWih[(k + 3) * 512 + c1];
                #pragma unroll
                for (int r = 0; r < 8; ++r) {
                    const float4 v = ((const float4*)xin[r])[k >> 2];
                    A0[r] = fmaf(u0, v.x, fmaf(u1, v.y, fmaf(u2, v.z, fmaf(u3, v.w, A0[r]))));
                    A1[r] = fmaf(w0, v.x, fmaf(w1, v.y, fmaf(w2, v.z, fmaf(w3, v.w, A1[r]))));
                }
            }
            #pragma unroll 2
            for (int k = 0; k < 128; k += 4) {
                const float u0 = gT_eWhh[(k + 0) * 512 + c0];
                const float u1 = gT_eWhh[(k + 1) * 512 + c0];
                const float u2 = gT_eWhh[(k + 2) * 512 + c0];
                const float u3 = gT_eWhh[(k + 3) * 512 + c0];
                const float w0 = gT_eWhh[(k + 0) * 512 + c1];
                const float w1 = gT_eWhh[(k + 1) * 512 + c1];
                const float w2 = gT_eWhh[(k + 2) * 512 + c1];
                const float w3 = gT_eWhh[(k + 3) * 512 + c1];
                #pragma unroll
                for (int r = 0; r < 8; ++r) {
                    const float4 v = ((const float4*)hc[r])[k >> 2];
                    A0[r] = fmaf(u0, v.x, fmaf(u1, v.y, fmaf(u2, v.z, fmaf(u3, v.w, A0[r]))));
                    A1[r] = fmaf(w0, v.x, fmaf(w1, v.y, fmaf(w2, v.z, fmaf(w3, v.w, A1[r]))));
                }
            }
            #pragma unroll
            for (int r = 0; r < 8; ++r) { gsm[r][c0] = A0[r]; gsm[r][c1] = A1[r]; }
        }
        __syncthreads();

        // enc LSTM update
        for (int m = tid; m < 8 * 128; m += 256) {
            const int r = m >> 7, j = m & 127;
            const float c = sigm(gsm[r][j + 128]) * hc[r][128 + j]
                          + sigm(gsm[r][j]) * tanhf(gsm[r][j + 256]);
            hc[r][j]       = sigm(gsm[r][j + 384]) * tanhf(c);
            hc[r][128 + j] = c;
        }
        __syncthreads();

        // mid gates: g = h@mWih^T + hm@mWhh^T + b
        {
            const int c0 = tid, c1 = tid + 256;
            float A0[8], A1[8];
            const float b0 = mbih[c0] + mbhh[c0], b1 = mbih[c1] + mbhh[c1];
            #pragma unroll
            for (int r = 0; r < 8; ++r) { A0[r] = b0; A1[r] = b1; }
            #pragma unroll 2
            for (int k = 0; k < 128; k += 4) {
                const float u0 = gT_mWih[(k + 0) * 512 + c0];
                const float u1 = gT_mWih[(k + 1) * 512 + c0];
                const float u2 = gT_mWih[(k + 2) * 512 + c0];
                const float u3 = gT_mWih[(k + 3) * 512 + c0];
                const float w0 = gT_mWih[(k + 0) * 512 + c1];
                const float w1 = gT_mWih[(k + 1) * 512 + c1];
                const float w2 = gT_mWih[(k + 2) * 512 + c1];
                const float w3 = gT_mWih[(k + 3) * 512 + c1];
                #pragma unroll
                for (int r = 0; r < 8; ++r) {
                    const float4 v = ((const float4*)hc[r])[k >> 2];   // h part
                    A0[r] = fmaf(u0, v.x, fmaf(u1, v.y, fmaf(u2, v.z, fmaf(u3, v.w, A0[r]))));
                    A1[r] = fmaf(w0, v.x, fmaf(w1, v.y, fmaf(w2, v.z, fmaf(w3, v.w, A1[r]))));
                }
            }
            #pragma unroll 2
            for (int k = 0; k < 128; k += 4) {
                const float u0 = gT_mWhh[(k + 0) * 512 + c0];
                const float u1 = gT_mWhh[(k + 1) * 512 + c0];
                const float u2 = gT_mWhh[(k + 2) * 512 + c0];
                const float u3 = gT_mWhh[(k + 3) * 512 + c0];
                const float w0 = gT_mWhh[(k + 0) * 512 + c1];
                const float w1 = gT_mWhh[(k + 1) * 512 + c1];
                const float w2 = gT_mWhh[(k + 2) * 512 + c1];
                const float w3 = gT_mWhh[(k + 3) * 512 + c1];
                #pragma unroll
                for (int r = 0; r < 8; ++r) {
                    const float4 v = ((const float4*)hmc[r])[k >> 2];
                    A0[r] = fmaf(u0, v.x, fmaf(u1, v.y, fmaf(u2, v.z, fmaf(u3, v.w, A0[r]))));
                    A1[r] = fmaf(w0, v.x, fmaf(w1, v.y, fmaf(w2, v.z, fmaf(w3, v.w, A1[r]))));
                }
            }
            #pragma unroll
            for (int r = 0; r < 8; ++r) { gsm[r][c0] = A0[r]; gsm[r][c1] = A1[r]; }
        }
        __syncthreads();

        // mid LSTM update + store mid_out
        for (int m = tid; m < 8 * 128; m += 256) {
            const int r = m >> 7, j = m & 127;
            const float c = sigm(gsm[r][j + 128]) * hmc[r][128 + j]
                          + sigm(gsm[r][j]) * tanhf(gsm[r][j + 256]);
            const float h = sigm(gsm[r][j + 384]) * tanhf(c);
            hmc[r][j] = h; hmc[r][128 + j] = c;
            g_mid[((r0 + r) * TE + t) * NH + j] = h;
        }
        __syncthreads();
    }

    for (int i = tid; i < 8 * 128; i += 256) {
        const int r = i >> 7, j = i & 127;
        g_hm[(r0 + r) * NH + j] = hmc[r][j];
        g_cm[(r0 + r) * NH + j] = hmc[r][128 + j];
    }
}

// ---------------- Kernel 2: wx_mid = mid_out @ Wx^T + Wx_b ----------------
__global__ __launch_bounds__(256, 1)
void k_wx(const float* __restrict__ Wx_b)
{
    __shared__ __align__(16) float ms[32][128];
    const int tid  = threadIdx.x;
    const int base = blockIdx.x * 32 * NH;

    for (int i = tid; i < 32 * 128; i += 256)
        ms[i >> 7][i & 127] = g_mid[base + i];
    __syncthreads();

    const int j = tid & 127, rg = tid >> 7;
    float acc[16];
    const float b = Wx_b[j];
    #pragma unroll
    for (int r = 0; r < 16; ++r) acc[r] = b;
    #pragma unroll 2
    for (int k = 0; k < 128; k += 4) {
        const float w0 = gT_Wx[(k + 0) * 128 + j];
        const float w1 = gT_Wx[(k + 1) * 128 + j];
        const float w2 = gT_Wx[(k + 2) * 128 + j];
        const float w3 = gT_Wx[(k + 3) * 128 + j];
        #pragma unroll
        for (int r = 0; r < 16; ++r) {
            const float4 v = ((const float4*)ms[rg * 16 + r])[k >> 2];
            acc[r] = fmaf(w0, v.x, fmaf(w1, v.y, fmaf(w2, v.z, fmaf(w3, v.w, acc[r]))));
        }
    }
    #pragma unroll
    for (int r = 0; r < 16; ++r)
        g_wx[base + (rg * 16 + r) * NH + j] = acc[r];
}

// ---------------- Kernel 3: temporal-attention decoder + head ----------------
__global__ __launch_bounds__(256, 1)
void k_dec(const float* __restrict__ V_w,  const float* __restrict__ V_b,
           const float* __restrict__ dbih, const float* __restrict__ dbhh,
           const float* __restrict__ regw, const float* __restrict__ regb,
           float* __restrict__ out)
{
    __shared__ __align__(16) float hic[8][256];
    __shared__ __align__(16) float qs [8][128];
    __shared__             float ss [8][TE];
    __shared__ __align__(16) float din[8][128];
    __shared__ __align__(16) float gsm[8][512];

    const int tid = threadIdx.x;
    const int r0  = blockIdx.x * 8;
    const int wno = tid >> 5, lane = tid & 31;

    // hoist V_w into registers (128 floats / 32 lanes = float4 each)
    const float4 vw4 = ((const float4*)V_w)[lane];
    const float  vb  = V_b[0];

    for (int i = tid; i < 8 * 256; i += 256) {
        const int r = i >> 8, k = i & 255;
        hic[r][k] = (k < 128) ? g_hm[(r0 + r) * NH + k]
                              : g_cm[(r0 + r) * NH + (k - 128)];
    }
    __syncthreads();

    for (int td = 0; td < TD; ++td) {
        // q = [hi,ci] @ Wh^T
        {
            const int j = tid & 127, rb = (tid >> 7) * 4;
            float a0 = 0.f, a1 = 0.f, a2 = 0.f, a3 = 0.f;
            #pragma unroll 4
            for (int k = 0; k < 256; k += 4) {
                const float w0 = gT_Wh[(k + 0) * 128 + j];
                const float w1 = gT_Wh[(k + 1) * 128 + j];
                const float w2 = gT_Wh[(k + 2) * 128 + j];
                const float w3 = gT_Wh[(k + 3) * 128 + j];
                float4 v;
                v = ((const float4*)hic[rb + 0])[k >> 2];
                a0 = fmaf(w0, v.x, fmaf(w1, v.y, fmaf(w2, v.z, fmaf(w3, v.w, a0))));
                v = ((const float4*)hic[rb + 1])[k >> 2];
                a1 = fmaf(w0, v.x, fmaf(w1, v.y, fmaf(w2, v.z, fmaf(w3, v.w, a1))));
                v = ((const float4*)hic[rb + 2])[k >> 2];
                a2 = fmaf(w0, v.x, fmaf(w1, v.y, fmaf(w2, v.z, fmaf(w3, v.w, a2))));
                v = ((const float4*)hic[rb + 3])[k >> 2];
                a3 = fmaf(w0, v.x, fmaf(w1, v.y, fmaf(w2, v.z, fmaf(w3, v.w, a3))));
            }
            qs[rb + 0][j] = a0; qs[rb + 1][j] = a1;
            qs[rb + 2][j] = a2; qs[rb + 3][j] = a3;
        }
        __syncthreads();

        // scores: warp per score, lanes over H (coalesced g_wx reads)
        for (int sc = wno; sc < 8 * TE; sc += 8) {
            const int r = sc / TE, tt = sc % TE;
            const float4 x = ((const float4*)(g_wx + ((r0 + r) * TE + tt) * NH))[lane];
            const float4 q = ((const float4*)qs[r])[lane];
            float acc;
            acc =      tanhf(q.x + x.x) * vw4.x;
            acc = fmaf(tanhf(q.y + x.y), vw4.y, acc);
            acc = fmaf(tanhf(q.z + x.z), vw4.z, acc);
            acc = fmaf(tanhf(q.w + x.w), vw4.w, acc);
            #pragma unroll
            for (int o = 16; o; o >>= 1) acc += __shfl_xor_sync(~0u, acc, o);
            if (lane == 0) ss[r][tt] = acc + vb;
        }
        __syncthreads();

        // dec_in[j] = sum_t ss[t] * mid[t][j]
        {
            const int j = tid & 127, rb = (tid >> 7) * 4;
            float a0 = 0.f, a1 = 0.f, a2 = 0.f, a3 = 0.f;
            const float* m0 = g_mid + (r0 + rb + 0) * TE * NH + j;
            const float* m1 = g_mid + (r0 + rb + 1) * TE * NH + j;
            const float* m2 = g_mid + (r0 + rb + 2) * TE * NH + j;
            const float* m3 = g_mid + (r0 + rb + 3) * TE * NH + j;
            for (int tt = 0; tt < TE; ++tt) {
                a0 = fmaf(ss[rb + 0][tt], m0[tt * NH], a0);
                a1 = fmaf(ss[rb + 1][tt], m1[tt * NH], a1);
                a2 = fmaf(ss[rb + 2][tt], m2[tt * NH], a2);
                a3 = fmaf(ss[rb + 3][tt], m3[tt * NH], a3);
            }
            din[rb + 0][j] = a0; din[rb + 1][j] = a1;
            din[rb + 2][j] = a2; din[rb + 3][j] = a3;
        }
        __syncthreads();

        // dec gates
        {
            const int c0 = tid, c1 = tid + 256;
            float A0[8], A1[8];
            const float b0 = dbih[c0] + dbhh[c0], b1 = dbih[c1] + dbhh[c1];
            #pragma unroll
            for (int r = 0; r < 8; ++r) { A0[r] = b0; A1[r] = b1; }
            #pragma unroll 2
            for (int k = 0; k < 128; k += 4) {
                const float u0 = gT_dWih[(k + 0) * 512 + c0];
                const float u1 = gT_dWih[(k + 1) * 512 + c0];
                const float u2 = gT_dWih[(k + 2) * 512 + c0];
                const float u3 = gT_dWih[(k + 3) * 512 + c0];
                const float w0 = gT_dWih[(k + 0) * 512 + c1];
                const float w1 = gT_dWih[(k + 1) * 512 + c1];
                const float w2 = gT_dWih[(k + 2) * 512 + c1];
                const float w3 = gT_dWih[(k + 3) * 512 + c1];
                #pragma unroll
                for (int r = 0; r < 8; ++r) {
                    const float4 v = ((const float4*)din[r])[k >> 2];
                    A0[r] = fmaf(u0, v.x, fmaf(u1, v.y, fmaf(u2, v.z, fmaf(u3, v.w, A0[r]))));
                    A1[r] = fmaf(w0, v.x, fmaf(w1, v.y, fmaf(w2, v.z, fmaf(w3, v.w, A1[r]))));
                }
            }
            #pragma unroll 2
            for (int k = 0; k < 128; k += 4) {
                const float u0 = gT_dWhh[(k + 0) * 512 + c0];
                const float u1 = gT_dWhh[(k + 1) * 512 + c0];
                const float u2 = gT_dWhh[(k + 2) * 512 + c0];
                const float u3 = gT_dWhh[(k + 3) * 512 + c0];
                const float w0 = gT_dWhh[(k + 0) * 512 + c1];
                const float w1 = gT_dWhh[(k + 1) * 512 + c1];
                const float w2 = gT_dWhh[(k + 2) * 512 + c1];
                const float w3 = gT_dWhh[(k + 3) * 512 + c1];
                #pragma unroll
                for (int r = 0; r < 8; ++r) {
                    const float4 v = ((const float4*)hic[r])[k >> 2];
                    A0[r] = fmaf(u0, v.x, fmaf(u1, v.y, fmaf(u2, v.z, fmaf(u3, v.w, A0[r]))));
                    A1[r] = fmaf(w0, v.x, fmaf(w1, v.y, fmaf(w2, v.z, fmaf(w3, v.w, A1[r]))));
                }
            }
            #pragma unroll
            for (int r = 0; r < 8; ++r) { gsm[r][c0] = A0[r]; gsm[r][c1] = A1[r]; }
        }
        __syncthreads();

        // dec LSTM update
        for (int m = tid; m < 8 * 128; m += 256) {
            const int r = m >> 7, j = m & 127;
            const float c = sigm(gsm[r][j + 128]) * hic[r][128 + j]
                          + sigm(gsm[r][j]) * tanhf(gsm[r][j + 256]);
            hic[r][j]       = sigm(gsm[r][j + 384]) * tanhf(c);
            hic[r][128 + j] = c;
        }
        __syncthreads();

        // out[b, td] = hi . reg_w + reg_b
        {
            float acc =            hic[wno][lane]      * regw[lane];
            acc = fmaf(hic[wno][lane + 32], regw[lane + 32], acc);
            acc = fmaf(hic[wno][lane + 64], regw[lane + 64], acc);
            acc = fmaf(hic[wno][lane + 96], regw[lane + 96], acc);
            #pragma unroll
            for (int o = 16; o; o >>= 1) acc += __shfl_xor_sync(~0u, acc, o);
            if (lane == 0) out[(r0 + wno) * TD + td] = acc + regb[0];
        }
        __syncthreads();
    }
}

extern "C" void kernel_launch(void* const* d_in, const int* in_sizes, int n_in,
                              void* d_out, int out_size)
{
    const float* X    = (const float*)d_in[0];
    const float* Wi_w = (const float*)d_in[2];
    const float* Wi_b = (const float*)d_in[3];
    const float* We_w = (const float*)d_in[4];
    const float* Vd_w = (const float*)d_in[5];
    const float* Vd_b = (const float*)d_in[6];
    const float* eWih = (const float*)d_in[7];
    const float* eWhh = (const float*)d_in[8];
    const float* ebih = (const float*)d_in[9];
    const float* ebhh = (const float*)d_in[10];
    const float* mWih = (const float*)d_in[11];
    const float* mWhh = (const float*)d_in[12];
    const float* mbih = (const float*)d_in[13];
    const float* mbhh = (const float*)d_in[14];
    const float* Wx_w = (const float*)d_in[15];
    const float* Wx_b = (const float*)d_in[16];
    const float* Wh_w = (const float*)d_in[17];
    const float* V_w  = (const float*)d_in[18];
    const float* V_b  = (const float*)d_in[19];
    const float* dWih = (const float*)d_in[20];
    const float* dWhh = (const float*)d_in[21];
    const float* dbih = (const float*)d_in[22];
    const float* dbhh = (const float*)d_in[23];
    const float* regw = (const float*)d_in[24];
    const float* regb = (const float*)d_in[25];

    k_tr<<<128, 512>>>(eWih, eWhh, mWih, mWhh, dWih, dWhh,
                       We_w, Wi_w, Vd_w, Wh_w, Wx_w);
    k_enc_mid<<<NB / 8, 256>>>(X, Wi_b, Vd_b, ebih, ebhh, mbih, mbhh);
    k_wx<<<(NB * TE) / 32, 256>>>(Wx_b);
    k_dec<<<NB / 8, 256>>>(V_w, V_b, dbih, dbhh, regw, regb, (float*)d_out);
}

// round 6
// speedup vs baseline: 1.6415x; 1.3372x over previous
#include <cuda_runtime.h>
#include <math.h>

#define NB 1024
#define TE 168
#define TD 24
#define NF 64
#define NH 128

__device__ float g_mid[NB * TE * NH];
__device__ float g_wx [NB * TE * NH];
__device__ float g_hm [NB * NH];
__device__ float g_cm [NB * NH];

// float4-packed k-major weights: gT4[kg*C + c] = {W[c][4kg],...,W[c][4kg+3]}
__device__ float4 gT4_eWih[16 * 512];
__device__ float4 gT4_eWhh[32 * 512];
__device__ float4 gT4_mWih[32 * 512];
__device__ float4 gT4_mWhh[32 * 512];
__device__ float4 gT4_dWih[32 * 512];
__device__ float4 gT4_dWhh[32 * 512];
__device__ float4 gT4_We [64 * 128];
__device__ float4 gT4_Wi [16 * 128];
__device__ float4 gT4_Vd [32 * 64];
__device__ float4 gT4_Wh [64 * 128];
__device__ float4 gT4_Wx [32 * 128];

__device__ __forceinline__ float ftanh(float x) {
    x = fminf(15.0f, fmaxf(-15.0f, x));
    const float e = __expf(2.0f * x);
    return __fdividef(e - 1.0f, e + 1.0f);
}
__device__ __forceinline__ float fsigm(float x) {
    return __fdividef(1.0f, 1.0f + __expf(-x));
}
__device__ __forceinline__ void fma4(float& acc, const float4 a, const float4 b) {
    acc = fmaf(a.x, b.x, fmaf(a.y, b.y, fmaf(a.z, b.z, fmaf(a.w, b.w, acc))));
}

// ---------------- Kernel 0: pack weights ----------------
__device__ __forceinline__ void packW(const float* __restrict__ W, float4* dst,
                                      int C, int K, int i0, int st)
{
    const int n = C * (K >> 2);
    for (int i = i0; i < n; i += st) {
        const int c = i % C, kg = i / C;
        const float* p = W + c * K + kg * 4;
        dst[i] = make_float4(p[0], p[1], p[2], p[3]);
    }
}

__global__ void k_tr(const float* __restrict__ eWih, const float* __restrict__ eWhh,
                     const float* __restrict__ mWih, const float* __restrict__ mWhh,
                     const float* __restrict__ dWih, const float* __restrict__ dWhh,
                     const float* __restrict__ We,   const float* __restrict__ Wi,
                     const float* __restrict__ Vd,   const float* __restrict__ Wh,
                     const float* __restrict__ Wx)
{
    const int i0 = blockIdx.x * blockDim.x + threadIdx.x;
    const int st = gridDim.x * blockDim.x;
    packW(eWih, gT4_eWih, 512, 64,  i0, st);
    packW(eWhh, gT4_eWhh, 512, 128, i0, st);
    packW(mWih, gT4_mWih, 512, 128, i0, st);
    packW(mWhh, gT4_mWhh, 512, 128, i0, st);
    packW(dWih, gT4_dWih, 512, 128, i0, st);
    packW(dWhh, gT4_dWhh, 512, 128, i0, st);
    packW(We,   gT4_We,   128, 256, i0, st);
    packW(Wi,   gT4_Wi,   128, 64,  i0, st);
    packW(Vd,   gT4_Vd,   64,  128, i0, st);
    packW(Wh,   gT4_Wh,   128, 256, i0, st);
    packW(Wx,   gT4_Wx,   128, 128, i0, st);
}

// ---------------- Kernel 1: encoder (attention LSTM) + mid LSTM ----------------
__global__ __launch_bounds__(512, 1)
void k_enc_mid(const float* __restrict__ X,
               const float* __restrict__ Wi_b, const float* __restrict__ Vd_b,
               const float* __restrict__ ebih, const float* __restrict__ ebhh,
               const float* __restrict__ mbih, const float* __restrict__ mbhh)
{
    __shared__ __align__(16) float hc [8][256];   // enc [h|c]
    __shared__ __align__(16) float hmc[8][256];   // mid [h|c]
    __shared__ __align__(16) float xt [8][64];
    __shared__ __align__(16) float t1s[8][128];
    __shared__ __align__(16) float ssm[8][64];
    __shared__ __align__(16) float xin[8][64];
    __shared__ __align__(16) float gsm[8][512];

    const int tid = threadIdx.x;
    const int r0  = blockIdx.x * 8;

    for (int i = tid; i < 8 * 256; i += 512) {
        hc[i >> 8][i & 255] = 0.0f;
        hmc[i >> 8][i & 255] = 0.0f;
    }
    __syncthreads();

    for (int t = 0; t < TE; ++t) {
        // one element per thread (8*64 = 512)
        xt[tid >> 6][tid & 63] = X[((r0 + (tid >> 6)) * TE + t) * NF + (tid & 63)];
        __syncthreads();

        // t1 = tanh([h,c]@We^T + x@Wi^T + Wi_b)  : 2 rows per thread
        {
            const int j = tid & 127, rb = (tid >> 7) * 2;
            float a0 = Wi_b[j], a1 = a0;
            const float4* p0 = (const float4*)hc[rb];
            const float4* p1 = (const float4*)hc[rb + 1];
            #pragma unroll 8
            for (int kg = 0; kg < 64; ++kg) {
                const float4 w = gT4_We[kg * 128 + j];
                fma4(a0, w, p0[kg]);
                fma4(a1, w, p1[kg]);
            }
            const float4* q0 = (const float4*)xt[rb];
            const float4* q1 = (const float4*)xt[rb + 1];
            #pragma unroll
            for (int kg = 0; kg < 16; ++kg) {
                const float4 w = gT4_Wi[kg * 128 + j];
                fma4(a0, w, q0[kg]);
                fma4(a1, w, q1[kg]);
            }
            t1s[rb][j]     = ftanh(a0);
            t1s[rb + 1][j] = ftanh(a1);
        }
        __syncthreads();

        // s = t1 @ Vd^T + Vd_b : 1 row per thread (8*64 = 512)
        {
            const int f = tid & 63, r = tid >> 6;
            float a = Vd_b[f];
            const float4* p = (const float4*)t1s[r];
            #pragma unroll 8
            for (int kg = 0; kg < 32; ++kg)
                fma4(a, gT4_Vd[kg * 64 + f], p[kg]);
            ssm[r][f] = a;
        }
        __syncthreads();

        // x_in = x * softmax(s)  (warps 0..7, one per row)
        {
            const int w = tid >> 5, lane = tid & 31;
            if (w < 8) {
                float v0 = ssm[w][lane], v1 = ssm[w][lane + 32];
                float mx = fmaxf(v0, v1);
                #pragma unroll
                for (int o = 16; o; o >>= 1) mx = fmaxf(mx, __shfl_xor_sync(~0u, mx, o));
                float e0 = __expf(v0 - mx), e1 = __expf(v1 - mx);
                float sm = e0 + e1;
                #pragma unroll
                for (int o = 16; o; o >>= 1) sm += __shfl_xor_sync(~0u, sm, o);
                float inv = __fdividef(1.0f, sm);
                xin[w][lane]      = xt[w][lane]      * e0 * inv;
                xin[w][lane + 32] = xt[w][lane + 32] * e1 * inv;
            }
        }
        __syncthreads();

        // enc gates: one gate column per thread
        {
            const int c = tid;
            float A[8];
            const float b = ebih[c] + ebhh[c];
            #pragma unroll
            for (int r = 0; r < 8; ++r) A[r] = b;
            #pragma unroll 4
            for (int kg = 0; kg < 16; ++kg) {
                const float4 w = gT4_eWih[kg * 512 + c];
                #pragma unroll
                for (int r = 0; r < 8; ++r)
                    fma4(A[r], w, ((const float4*)xin[r])[kg]);
            }
            #pragma unroll 4
            for (int kg = 0; kg < 32; ++kg) {
                const float4 w = gT4_eWhh[kg * 512 + c];
                #pragma unroll
                for (int r = 0; r < 8; ++r)
                    fma4(A[r], w, ((const float4*)hc[r])[kg]);
            }
            #pragma unroll
            for (int r = 0; r < 8; ++r) gsm[r][c] = A[r];
        }
        __syncthreads();

        // enc LSTM update (2 elems per thread)
        for (int m = tid; m < 8 * 128; m += 512) {
            const int r = m >> 7, j = m & 127;
            const float c = fsigm(gsm[r][j + 128]) * hc[r][128 + j]
                          + fsigm(gsm[r][j]) * ftanh(gsm[r][j + 256]);
            hc[r][j]       = fsigm(gsm[r][j + 384]) * ftanh(c);
            hc[r][128 + j] = c;
        }
        __syncthreads();

        // mid gates
        {
            const int c = tid;
            float A[8];
            const float b = mbih[c] + mbhh[c];
            #pragma unroll
            for (int r = 0; r < 8; ++r) A[r] = b;
            #pragma unroll 4
            for (int kg = 0; kg < 32; ++kg) {
                const float4 w = gT4_mWih[kg * 512 + c];
                #pragma unroll
                for (int r = 0; r < 8; ++r)
                    fma4(A[r], w, ((const float4*)hc[r])[kg]);   // h part
            }
            #pragma unroll 4
            for (int kg = 0; kg < 32; ++kg) {
                const float4 w = gT4_mWhh[kg * 512 + c];
                #pragma unroll
                for (int r = 0; r < 8; ++r)
                    fma4(A[r], w, ((const float4*)hmc[r])[kg]);
            }
            #pragma unroll
            for (int r = 0; r < 8; ++r) gsm[r][c] = A[r];
        }
        __syncthreads();

        // mid LSTM update + store mid_out
        for (int m = tid; m < 8 * 128; m += 512) {
            const int r = m >> 7, j = m & 127;
            const float c = fsigm(gsm[r][j + 128]) * hmc[r][128 + j]
                          + fsigm(gsm[r][j]) * ftanh(gsm[r][j + 256]);
            const float h = fsigm(gsm[r][j + 384]) * ftanh(c);
            hmc[r][j] = h; hmc[r][128 + j] = c;
            g_mid[((r0 + r) * TE + t) * NH + j] = h;
        }
        __syncthreads();
    }

    for (int m = tid; m < 8 * 128; m += 512) {
        const int r = m >> 7, j = m & 127;
        g_hm[(r0 + r) * NH + j] = hmc[r][j];
        g_cm[(r0 + r) * NH + j] = hmc[r][128 + j];
    }
}

// ---------------- Kernel 2: wx_mid = mid_out @ Wx^T + Wx_b ----------------
__global__ __launch_bounds__(256, 1)
void k_wx(const float* __restrict__ Wx_b)
{
    __shared__ __align__(16) float ms[32][128];
    const int tid  = threadIdx.x;
    const int base = blockIdx.x * 32 * NH;

    for (int i = tid; i < 32 * 128; i += 256)
        ms[i >> 7][i & 127] = g_mid[base + i];
    __syncthreads();

    const int j = tid & 127, rg = tid >> 7;
    float acc[16];
    const float b = Wx_b[j];
    #pragma unroll
    for (int r = 0; r < 16; ++r) acc[r] = b;
    #pragma unroll 4
    for (int kg = 0; kg < 32; ++kg) {
        const float4 w = gT4_Wx[kg * 128 + j];
        #pragma unroll
        for (int r = 0; r < 16; ++r)
            fma4(acc[r], w, ((const float4*)ms[rg * 16 + r])[kg]);
    }
    #pragma unroll
    for (int r = 0; r < 16; ++r)
        g_wx[base + (rg * 16 + r) * NH + j] = acc[r];
}

// ---------------- Kernel 3: temporal-attention decoder + head ----------------
__global__ __launch_bounds__(512, 1)
void k_dec(const float* __restrict__ V_w,  const float* __restrict__ V_b,
           const float* __restrict__ dbih, const float* __restrict__ dbhh,
           const float* __restrict__ regw, const float* __restrict__ regb,
           float* __restrict__ out)
{
    __shared__ __align__(16) float hic[8][256];
    __shared__ __align__(16) float qs [8][128];
    __shared__             float ss [8][TE];
    __shared__ __align__(16) float din[8][128];
    __shared__ __align__(16) float gsm[8][512];

    const int tid = threadIdx.x;
    const int r0  = blockIdx.x * 8;
    const int wno = tid >> 5, lane = tid & 31;

    const float4 vw4 = ((const float4*)V_w)[lane];
    const float  vb  = V_b[0];

    for (int i = tid; i < 8 * 256; i += 512) {
        const int r = i >> 8, k = i & 255;
        hic[r][k] = (k < 128) ? g_hm[(r0 + r) * NH + k]
                              : g_cm[(r0 + r) * NH + (k - 128)];
    }
    __syncthreads();

    for (int td = 0; td < TD; ++td) {
        // q = [hi,ci] @ Wh^T : 2 rows per thread
        {
            const int j = tid & 127, rb = (tid >> 7) * 2;
            float a0 = 0.f, a1 = 0.f;
            const float4* p0 = (const float4*)hic[rb];
            const float4* p1 = (const float4*)hic[rb + 1];
            #pragma unroll 8
            for (int kg = 0; kg < 64; ++kg) {
                const float4 w = gT4_Wh[kg * 128 + j];
                fma4(a0, w, p0[kg]);
                fma4(a1, w, p1[kg]);
            }
            qs[rb][j] = a0; qs[rb + 1][j] = a1;
        }
        __syncthreads();

        // scores: warp per score, lanes over H
        for (int sc = wno; sc < 8 * TE; sc += 16) {
            const int r = sc / TE, tt = sc % TE;
            const float4 x = ((const float4*)(g_wx + ((r0 + r) * TE + tt) * NH))[lane];
            const float4 q = ((const float4*)qs[r])[lane];
            float acc;
            acc =      ftanh(q.x + x.x) * vw4.x;
            acc = fmaf(ftanh(q.y + x.y), vw4.y, acc);
            acc = fmaf(ftanh(q.z + x.z), vw4.z, acc);
            acc = fmaf(ftanh(q.w + x.w), vw4.w, acc);
            #pragma unroll
            for (int o = 16; o; o >>= 1) acc += __shfl_xor_sync(~0u, acc, o);
            if (lane == 0) ss[r][tt] = acc + vb;
        }
        __syncthreads();

        // dec_in[j] = sum_t ss[t] * mid[t][j] : 2 rows per thread
        {
            const int j = tid & 127, rb = (tid >> 7) * 2;
            float a0 = 0.f, a1 = 0.f;
            const float* m0 = g_mid + (r0 + rb)     * TE * NH + j;
            const float* m1 = g_mid + (r0 + rb + 1) * TE * NH + j;
            for (int tt = 0; tt < TE; ++tt) {
                a0 = fmaf(ss[rb][tt],     m0[tt * NH], a0);
                a1 = fmaf(ss[rb + 1][tt], m1[tt * NH], a1);
            }
            din[rb][j] = a0; din[rb + 1][j] = a1;
        }
        __syncthreads();

        // dec gates: one column per thread
        {
            const int c = tid;
            float A[8];
            const float b = dbih[c] + dbhh[c];
            #pragma unroll
            for (int r = 0; r < 8; ++r) A[r] = b;
            #pragma unroll 4
            for (int kg = 0; kg < 32; ++kg) {
                const float4 w = gT4_dWih[kg * 512 + c];
                #pragma unroll
                for (int r = 0; r < 8; ++r)
                    fma4(A[r], w, ((const float4*)din[r])[kg]);
            }
            #pragma unroll 4
            for (int kg = 0; kg < 32; ++kg) {
                const float4 w = gT4_dWhh[kg * 512 + c];
                #pragma unroll
                for (int r = 0; r < 8; ++r)
                    fma4(A[r], w, ((const float4*)hic[r])[kg]);
            }
            #pragma unroll
            for (int r = 0; r < 8; ++r) gsm[r][c] = A[r];
        }
        __syncthreads();

        // dec LSTM update
        for (int m = tid; m < 8 * 128; m += 512) {
            const int r = m >> 7, j = m & 127;
            const float c = fsigm(gsm[r][j + 128]) * hic[r][128 + j]
                          + fsigm(gsm[r][j]) * ftanh(gsm[r][j + 256]);
            hic[r][j]       = fsigm(gsm[r][j + 384]) * ftanh(c);
            hic[r][128 + j] = c;
        }
        __syncthreads();

        // out[b, td] = hi . reg_w + reg_b  (warps 0..7)
        if (wno < 8) {
            float acc =            hic[wno][lane]      * regw[lane];
            acc = fmaf(hic[wno][lane + 32], regw[lane + 32], acc);
            acc = fmaf(hic[wno][lane + 64], regw[lane + 64], acc);
            acc = fmaf(hic[wno][lane + 96], regw[lane + 96], acc);
            #pragma unroll
            for (int o = 16; o; o >>= 1) acc += __shfl_xor_sync(~0u, acc, o);
            if (lane == 0) out[(r0 + wno) * TD + td] = acc + regb[0];
        }
        __syncthreads();
    }
}

extern "C" void kernel_launch(void* const* d_in, const int* in_sizes, int n_in,
                              void* d_out, int out_size)
{
    const float* X    = (const float*)d_in[0];
    const float* Wi_w = (const float*)d_in[2];
    const float* Wi_b = (const float*)d_in[3];
    const float* We_w = (const float*)d_in[4];
    const float* Vd_w = (const float*)d_in[5];
    const float* Vd_b = (const float*)d_in[6];
    const float* eWih = (const float*)d_in[7];
    const float* eWhh = (const float*)d_in[8];
    const float* ebih = (const float*)d_in[9];
    const float* ebhh = (const float*)d_in[10];
    const float* mWih = (const float*)d_in[11];
    const float* mWhh = (const float*)d_in[12];
    const float* mbih = (const float*)d_in[13];
    const float* mbhh = (const float*)d_in[14];
    const float* Wx_b = (const float*)d_in[16];
    const float* Wh_w = (const float*)d_in[17];
    const float* V_w  = (const float*)d_in[18];
    const float* V_b  = (const float*)d_in[19];
    const float* dWih = (const float*)d_in[20];
    const float* dWhh = (const float*)d_in[21];
    const float* dbih = (const float*)d_in[22];
    const float* dbhh = (const float*)d_in[23];
    const float* regw = (const float*)d_in[24];
    const float* regb = (const float*)d_in[25];
    const float* Wx_w = (const float*)d_in[15];

    k_tr<<<256, 256>>>(eWih, eWhh, mWih, mWhh, dWih, dWhh,
                       We_w, Wi_w, Vd_w, Wh_w, Wx_w);
    k_enc_mid<<<NB / 8, 512>>>(X, Wi_b, Vd_b, ebih, ebhh, mbih, mbhh);
    k_wx<<<(NB * TE) / 32, 256>>>(Wx_b);
    k_dec<<<NB / 8, 512>>>(V_w, V_b, dbih, dbhh, regw, regb, (float*)d_out);
}

// round 7
// speedup vs baseline: 1.7805x; 1.0847x over previous
#include <cuda_runtime.h>
#include <math.h>

#define NB 1024
#define TE 168
#define TD 24
#define NF 64
#define NH 128

typedef unsigned long long u64;

// ---- paired (row-pair) globals ----
__device__ float2 g_midp[(NB/2) * TE * NH];   // {h[2p], h[2p+1]}
__device__ float  g_wx  [NB * TE * NH];       // row-major fp32
__device__ float2 g_hmp [(NB/2) * NH];
__device__ float2 g_cmp [(NB/2) * NH];

// float4-packed k-major weights: gT4[kg*C + c] = {W[c][4kg..4kg+3]}
__device__ float4 gT4_eWih[16 * 512];
__device__ float4 gT4_eWhh[32 * 512];
__device__ float4 gT4_mWih[32 * 512];
__device__ float4 gT4_mWhh[32 * 512];
__device__ float4 gT4_dWih[32 * 512];
__device__ float4 gT4_dWhh[32 * 512];
__device__ float4 gT4_We [64 * 128];
__device__ float4 gT4_Wi [16 * 128];
__device__ float4 gT4_Vd [32 * 64];
__device__ float4 gT4_Wh [64 * 128];
__device__ float4 gT4_Wx [32 * 128];

__device__ __forceinline__ float ftanh(float x) {
    x = fminf(15.0f, fmaxf(-15.0f, x));
    const float e = __expf(2.0f * x);
    return __fdividef(e - 1.0f, e + 1.0f);
}
__device__ __forceinline__ float fsigm(float x) {
    return __fdividef(1.0f, 1.0f + __expf(-x));
}

// ---- f32x2 packed helpers ----
__device__ __forceinline__ u64 dup2(float x) {
    u64 r; asm("mov.b64 %0, {%1, %1};" : "=l"(r) : "f"(x)); return r;
}
__device__ __forceinline__ float2 unp2(u64 v) {
    float2 r; asm("mov.b64 {%0, %1}, %2;" : "=f"(r.x), "=f"(r.y) : "l"(v)); return r;
}
__device__ __forceinline__ void ffma2(u64& d, u64 a, u64 b) {
    asm("fma.rn.f32x2 %0, %1, %2, %0;" : "+l"(d) : "l"(a), "l"(b));
}

// ---------------- Kernel 0: pack weights (k-major float4) ----------------
__device__ __forceinline__ void packW(const float* __restrict__ W, float4* dst,
                                      int C, int K, int i0, int st)
{
    const int n = C * (K >> 2);
    for (int i = i0; i < n; i += st) {
        const int c = i % C, kg = i / C;
        const float* p = W + c * K + kg * 4;
        dst[i] = make_float4(p[0], p[1], p[2], p[3]);
    }
}

__global__ void k_tr(const float* __restrict__ eWih, const float* __restrict__ eWhh,
                     const float* __restrict__ mWih, const float* __restrict__ mWhh,
                     const float* __restrict__ dWih, const float* __restrict__ dWhh,
                     const float* __restrict__ We,   const float* __restrict__ Wi,
                     const float* __restrict__ Vd,   const float* __restrict__ Wh,
                     const float* __restrict__ Wx)
{
    const int i0 = blockIdx.x * blockDim.x + threadIdx.x;
    const int st = gridDim.x * blockDim.x;
    packW(eWih, gT4_eWih, 512, 64,  i0, st);
    packW(eWhh, gT4_eWhh, 512, 128, i0, st);
    packW(mWih, gT4_mWih, 512, 128, i0, st);
    packW(mWhh, gT4_mWhh, 512, 128, i0, st);
    packW(dWih, gT4_dWih, 512, 128, i0, st);
    packW(dWhh, gT4_dWhh, 512, 128, i0, st);
    packW(We,   gT4_We,   128, 256, i0, st);
    packW(Wi,   gT4_Wi,   128, 64,  i0, st);
    packW(Vd,   gT4_Vd,   64,  128, i0, st);
    packW(Wh,   gT4_Wh,   128, 256, i0, st);
    packW(Wx,   gT4_Wx,   128, 128, i0, st);
}

// inner product block: acc += W4 (dup'd) * paired activations at kg
__device__ __forceinline__ void gemm_kg(u64& acc, const float4 w,
                                        const ulonglong2* __restrict__ act, int kg)
{
    const u64 w0 = dup2(w.x), w1 = dup2(w.y), w2 = dup2(w.z), w3 = dup2(w.w);
    const ulonglong2 a01 = act[2 * kg];
    const ulonglong2 a23 = act[2 * kg + 1];
    ffma2(acc, w0, a01.x); ffma2(acc, w1, a01.y);
    ffma2(acc, w2, a23.x); ffma2(acc, w3, a23.y);
}

// ---------------- Kernel 1: encoder (attention LSTM) + mid LSTM ----------------
__global__ __launch_bounds__(512, 1)
void k_enc_mid(const float* __restrict__ X,
               const float* __restrict__ Wi_b, const float* __restrict__ Vd_b,
               const float* __restrict__ ebih, const float* __restrict__ ebhh,
               const float* __restrict__ mbih, const float* __restrict__ mbhh)
{
    __shared__ __align__(16) float2 hcp [4][256];   // enc [h|c] paired
    __shared__ __align__(16) float2 hmcp[4][256];   // mid [h|c] paired
    __shared__ __align__(16) float2 xtp [4][64];
    __shared__ __align__(16) float2 t1p [4][128];
    __shared__ __align__(16) float2 sspr[4][64];
    __shared__ __align__(16) float2 xinp[4][64];
    __shared__ __align__(16) float2 gsmp[4][512];

    const int tid = threadIdx.x;
    const int r0  = blockIdx.x * 8;
    const int p0  = blockIdx.x * 4;

    for (int i = tid; i < 4 * 256; i += 512) {
        hcp [i >> 8][i & 255] = make_float2(0.f, 0.f);
        hmcp[i >> 8][i & 255] = make_float2(0.f, 0.f);
    }
    __syncthreads();

    for (int t = 0; t < TE; ++t) {
        // load x_t into paired layout: tid -> (half, rp, f)
        {
            const int f = tid & 63, rp = (tid >> 6) & 3, half = tid >> 8;
            ((float*)&xtp[rp][f])[half] = X[((r0 + 2 * rp + half) * TE + t) * NF + f];
        }
        __syncthreads();

        // t1 = tanh([h,c]@We^T + x@Wi^T + Wi_b) : thread = (j, rp)
        {
            const int j = tid & 127, rp = tid >> 7;
            u64 acc = dup2(Wi_b[j]);
            const ulonglong2* hp = (const ulonglong2*)hcp[rp];
            #pragma unroll 8
            for (int kg = 0; kg < 64; ++kg)
                gemm_kg(acc, gT4_We[kg * 128 + j], hp, kg);
            const ulonglong2* xp = (const ulonglong2*)xtp[rp];
            #pragma unroll
            for (int kg = 0; kg < 16; ++kg)
                gemm_kg(acc, gT4_Wi[kg * 128 + j], xp, kg);
            const float2 r = unp2(acc);
            t1p[rp][j] = make_float2(ftanh(r.x), ftanh(r.y));
        }
        __syncthreads();

        // s = t1 @ Vd^T + Vd_b : thread = (f, rp), 256 active
        if (tid < 256) {
            const int f = tid & 63, rp = tid >> 6;
            u64 acc = dup2(Vd_b[f]);
            const ulonglong2* tp = (const ulonglong2*)t1p[rp];
            #pragma unroll 8
            for (int kg = 0; kg < 32; ++kg)
                gemm_kg(acc, gT4_Vd[kg * 64 + f], tp, kg);
            sspr[rp][f] = unp2(acc);
        }
        __syncthreads();

        // softmax + x_in : warp w handles row w (rp = w>>1, half = w&1)
        {
            const int w = tid >> 5, lane = tid & 31;
            if (w < 8) {
                const int rp = w >> 1, half = w & 1;
                const float2 s0 = sspr[rp][lane], s1 = sspr[rp][lane + 32];
                float v0 = half ? s0.y : s0.x;
                float v1 = half ? s1.y : s1.x;
                float mx = fmaxf(v0, v1);
                #pragma unroll
                for (int o = 16; o; o >>= 1) mx = fmaxf(mx, __shfl_xor_sync(~0u, mx, o));
                float e0 = __expf(v0 - mx), e1 = __expf(v1 - mx);
                float sm = e0 + e1;
                #pragma unroll
                for (int o = 16; o; o >>= 1) sm += __shfl_xor_sync(~0u, sm, o);
                const float inv = __fdividef(1.0f, sm);
                const float2 x0 = xtp[rp][lane], x1 = xtp[rp][lane + 32];
                ((float*)&xinp[rp][lane])[half]      = (half ? x0.y : x0.x) * e0 * inv;
                ((float*)&xinp[rp][lane + 32])[half] = (half ? x1.y : x1.x) * e1 * inv;
            }
        }
        __syncthreads();

        // enc gates: thread = gate column c, acc over 4 row-pairs
        {
            const int c = tid;
            const u64 bini = dup2(ebih[c] + ebhh[c]);
            u64 A0 = bini, A1 = bini, A2 = bini, A3 = bini;
            #pragma unroll 4
            for (int kg = 0; kg < 16; ++kg) {
                const float4 w = gT4_eWih[kg * 512 + c];
                gemm_kg(A0, w, (const ulonglong2*)xinp[0], kg);
                gemm_kg(A1, w, (const ulonglong2*)xinp[1], kg);
                gemm_kg(A2, w, (const ulonglong2*)xinp[2], kg);
                gemm_kg(A3, w, (const ulonglong2*)xinp[3], kg);
            }
            #pragma unroll 4
            for (int kg = 0; kg < 32; ++kg) {
                const float4 w = gT4_eWhh[kg * 512 + c];
                gemm_kg(A0, w, (const ulonglong2*)hcp[0], kg);
                gemm_kg(A1, w, (const ulonglong2*)hcp[1], kg);
                gemm_kg(A2, w, (const ulonglong2*)hcp[2], kg);
                gemm_kg(A3, w, (const ulonglong2*)hcp[3], kg);
            }
            gsmp[0][c] = unp2(A0); gsmp[1][c] = unp2(A1);
            gsmp[2][c] = unp2(A2); gsmp[3][c] = unp2(A3);
        }
        __syncthreads();

        // enc LSTM update : thread = (j, rp)
        {
            const int j = tid & 127, rp = tid >> 7;
            const float2 gi = gsmp[rp][j],       gf = gsmp[rp][j + 128];
            const float2 gg = gsmp[rp][j + 256], go = gsmp[rp][j + 384];
            const float2 co = hcp[rp][128 + j];
            float2 cn, hn;
            cn.x = fsigm(gf.x) * co.x + fsigm(gi.x) * ftanh(gg.x);
            cn.y = fsigm(gf.y) * co.y + fsigm(gi.y) * ftanh(gg.y);
            hn.x = fsigm(go.x) * ftanh(cn.x);
            hn.y = fsigm(go.y) * ftanh(cn.y);
            hcp[rp][j] = hn; hcp[rp][128 + j] = cn;
        }
        __syncthreads();

        // mid gates
        {
            const int c = tid;
            const u64 bini = dup2(mbih[c] + mbhh[c]);
            u64 A0 = bini, A1 = bini, A2 = bini, A3 = bini;
            #pragma unroll 4
            for (int kg = 0; kg < 32; ++kg) {
                const float4 w = gT4_mWih[kg * 512 + c];
                gemm_kg(A0, w, (const ulonglong2*)hcp[0], kg);
                gemm_kg(A1, w, (const ulonglong2*)hcp[1], kg);
                gemm_kg(A2, w, (const ulonglong2*)hcp[2], kg);
                gemm_kg(A3, w, (const ulonglong2*)hcp[3], kg);
            }
            #pragma unroll 4
            for (int kg = 0; kg < 32; ++kg) {
                const float4 w = gT4_mWhh[kg * 512 + c];
                gemm_kg(A0, w, (const ulonglong2*)hmcp[0], kg);
                gemm_kg(A1, w, (const ulonglong2*)hmcp[1], kg);
                gemm_kg(A2, w, (const ulonglong2*)hmcp[2], kg);
                gemm_kg(A3, w, (const ulonglong2*)hmcp[3], kg);
            }
            gsmp[0][c] = unp2(A0); gsmp[1][c] = unp2(A1);
            gsmp[2][c] = unp2(A2); gsmp[3][c] = unp2(A3);
        }
        __syncthreads();

        // mid LSTM update + paired g_mid store
        {
            const int j = tid & 127, rp = tid >> 7;
            const float2 gi = gsmp[rp][j],       gf = gsmp[rp][j + 128];
            const float2 gg = gsmp[rp][j + 256], go = gsmp[rp][j + 384];
            const float2 co = hmcp[rp][128 + j];
            float2 cn, hn;
            cn.x = fsigm(gf.x) * co.x + fsigm(gi.x) * ftanh(gg.x);
            cn.y = fsigm(gf.y) * co.y + fsigm(gi.y) * ftanh(gg.y);
            hn.x = fsigm(go.x) * ftanh(cn.x);
            hn.y = fsigm(go.y) * ftanh(cn.y);
            hmcp[rp][j] = hn; hmcp[rp][128 + j] = cn;
            g_midp[((p0 + rp) * TE + t) * NH + j] = hn;
        }
        __syncthreads();
    }

    {
        const int j = tid & 127, rp = tid >> 7;
        g_hmp[(p0 + rp) * NH + j] = hmcp[rp][j];
        g_cmp[(p0 + rp) * NH + j] = hmcp[rp][128 + j];
    }
}

// ---------------- Kernel 2: wx_mid = mid_out @ Wx^T + Wx_b ----------------
// tile = 16 (pair,t) units
__global__ __launch_bounds__(256, 1)
void k_wx(const float* __restrict__ Wx_b)
{
    __shared__ __align__(16) float2 msp[16][128];
    const int tid  = threadIdx.x;
    const int ub   = blockIdx.x * 16;           // base unit (pair*TE + t)

    for (int i = tid; i < 16 * 128; i += 256)
        msp[i >> 7][i & 127] = g_midp[ub * NH + i];
    __syncthreads();

    const int j = tid & 127, rg = tid >> 7;
    const u64 bini = dup2(Wx_b[j]);
    u64 acc[8];
    #pragma unroll
    for (int u = 0; u < 8; ++u) acc[u] = bini;

    #pragma unroll 4
    for (int kg = 0; kg < 32; ++kg) {
        const float4 w = gT4_Wx[kg * 128 + j];
        #pragma unroll
        for (int u = 0; u < 8; ++u)
            gemm_kg(acc[u], w, (const ulonglong2*)msp[rg * 8 + u], kg);
    }
    #pragma unroll
    for (int u = 0; u < 8; ++u) {
        const int gu = ub + rg * 8 + u;
        const int pair = gu / TE, tt = gu % TE;
        const float2 r = unp2(acc[u]);
        g_wx[((2 * pair)     * TE + tt) * NH + j] = r.x;
        g_wx[((2 * pair + 1) * TE + tt) * NH + j] = r.y;
    }
}

// ---------------- Kernel 3: temporal-attention decoder + head ----------------
__global__ __launch_bounds__(512, 1)
void k_dec(const float* __restrict__ V_w,  const float* __restrict__ V_b,
           const float* __restrict__ dbih, const float* __restrict__ dbhh,
           const float* __restrict__ regw, const float* __restrict__ regb,
           float* __restrict__ out)
{
    __shared__ __align__(16) float2 hicp[4][256];
    __shared__ __align__(16) float2 qsp [4][128];
    __shared__ __align__(16) float2 ssp2[4][TE];
    __shared__ __align__(16) float2 dinp[4][128];
    __shared__ __align__(16) float2 gsmp[4][512];

    const int tid = threadIdx.x;
    const int r0  = blockIdx.x * 8;
    const int p0  = blockIdx.x * 4;
    const int wno = tid >> 5, lane = tid & 31;

    const float4 vw4 = ((const float4*)V_w)[lane];
    const float  vb  = V_b[0];

    for (int i = tid; i < 4 * 256; i += 512) {
        const int rp = i >> 8, k = i & 255;
        hicp[rp][k] = (k < 128) ? g_hmp[(p0 + rp) * NH + k]
                                : g_cmp[(p0 + rp) * NH + (k - 128)];
    }
    __syncthreads();

    for (int td = 0; td < TD; ++td) {
        // q = [hi,ci] @ Wh^T : thread = (j, rp)
        {
            const int j = tid & 127, rp = tid >> 7;
            u64 acc = dup2(0.0f);
            const ulonglong2* hp = (const ulonglong2*)hicp[rp];
            #pragma unroll 8
            for (int kg = 0; kg < 64; ++kg)
                gemm_kg(acc, gT4_Wh[kg * 128 + j], hp, kg);
            qsp[rp][j] = unp2(acc);
        }
        __syncthreads();

        // scores: warp per (r, tt)
        for (int sc = wno; sc < 8 * TE; sc += 16) {
            const int r = sc / TE, tt = sc % TE;
            const int rp = r >> 1, half = r & 1;
            const float4 x = ((const float4*)(g_wx + ((r0 + r) * TE + tt) * NH))[lane];
            const float2 q0 = qsp[rp][4 * lane],     q1 = qsp[rp][4 * lane + 1];
            const float2 q2 = qsp[rp][4 * lane + 2], q3 = qsp[rp][4 * lane + 3];
            float acc;
            acc =      ftanh((half ? q0.y : q0.x) + x.x) * vw4.x;
            acc = fmaf(ftanh((half ? q1.y : q1.x) + x.y), vw4.y, acc);
            acc = fmaf(ftanh((half ? q2.y : q2.x) + x.z), vw4.z, acc);
            acc = fmaf(ftanh((half ? q3.y : q3.x) + x.w), vw4.w, acc);
            #pragma unroll
            for (int o = 16; o; o >>= 1) acc += __shfl_xor_sync(~0u, acc, o);
            if (lane == 0) ((float*)&ssp2[rp][tt])[half] = acc + vb;
        }
        __syncthreads();

        // dec_in = sum_t ss[t] * mid[t] : thread = (j, rp), packed
        {
            const int j = tid & 127, rp = tid >> 7;
            u64 acc = dup2(0.0f);
            const u64* sp = (const u64*)ssp2[rp];
            const float2* mp = g_midp + ((p0 + rp) * TE) * NH + j;
            #pragma unroll 4
            for (int tt = 0; tt < TE; ++tt) {
                const u64 m2 = *(const u64*)(mp + tt * NH);
                ffma2(acc, sp[tt], m2);
            }
            dinp[rp][j] = unp2(acc);
        }
        __syncthreads();

        // dec gates: thread = column c
        {
            const int c = tid;
            const u64 bini = dup2(dbih[c] + dbhh[c]);
            u64 A0 = bini, A1 = bini, A2 = bini, A3 = bini;
            #pragma unroll 4
            for (int kg = 0; kg < 32; ++kg) {
                const float4 w = gT4_dWih[kg * 512 + c];
                gemm_kg(A0, w, (const ulonglong2*)dinp[0], kg);
                gemm_kg(A1, w, (const ulonglong2*)dinp[1], kg);
                gemm_kg(A2, w, (const ulonglong2*)dinp[2], kg);
                gemm_kg(A3, w, (const ulonglong2*)dinp[3], kg);
            }
            #pragma unroll 4
            for (int kg = 0; kg < 32; ++kg) {
                const float4 w = gT4_dWhh[kg * 512 + c];
                gemm_kg(A0, w, (const ulonglong2*)hicp[0], kg);
                gemm_kg(A1, w, (const ulonglong2*)hicp[1], kg);
                gemm_kg(A2, w, (const ulonglong2*)hicp[2], kg);
                gemm_kg(A3, w, (const ulonglong2*)hicp[3], kg);
            }
            gsmp[0][c] = unp2(A0); gsmp[1][c] = unp2(A1);
            gsmp[2][c] = unp2(A2); gsmp[3][c] = unp2(A3);
        }
        __syncthreads();

        // dec LSTM update
        {
            const int j = tid & 127, rp = tid >> 7;
            const float2 gi = gsmp[rp][j],       gf = gsmp[rp][j + 128];
            const float2 gg = gsmp[rp][j + 256], go = gsmp[rp][j + 384];
            const float2 co = hicp[rp][128 + j];
            float2 cn, hn;
            cn.x = fsigm(gf.x) * co.x + fsigm(gi.x) * ftanh(gg.x);
            cn.y = fsigm(gf.y) * co.y + fsigm(gi.y) * ftanh(gg.y);
            hn.x = fsigm(go.x) * ftanh(cn.x);
            hn.y = fsigm(go.y) * ftanh(cn.y);
            hicp[rp][j] = hn; hicp[rp][128 + j] = cn;
        }
        __syncthreads();

        // out[b, td] : warp w handles row w
        if (wno < 8) {
            const int rp = wno >> 1, half = wno & 1;
            const float2 h0 = hicp[rp][lane],      h1 = hicp[rp][lane + 32];
            const float2 h2 = hicp[rp][lane + 64], h3 = hicp[rp][lane + 96];
            float acc =       (half ? h0.y : h0.x) * regw[lane];
            acc = fmaf((half ? h1.y : h1.x), regw[lane + 32], acc);
            acc = fmaf((half ? h2.y : h2.x), regw[lane + 64], acc);
            acc = fmaf((half ? h3.y : h3.x), regw[lane + 96], acc);
            #pragma unroll
            for (int o = 16; o; o >>= 1) acc += __shfl_xor_sync(~0u, acc, o);
            if (lane == 0) out[(r0 + wno) * TD + td] = acc + regb[0];
        }
        __syncthreads();
    }
}

extern "C" void kernel_launch(void* const* d_in, const int* in_sizes, int n_in,
                              void* d_out, int out_size)
{
    const float* X    = (const float*)d_in[0];
    const float* Wi_w = (const float*)d_in[2];
    const float* Wi_b = (const float*)d_in[3];
    const float* We_w = (const float*)d_in[4];
    const float* Vd_w = (const float*)d_in[5];
    const float* Vd_b = (const float*)d_in[6];
    const float* eWih = (const float*)d_in[7];
    const float* eWhh = (const float*)d_in[8];
    const float* ebih = (const float*)d_in[9];
    const float* ebhh = (const float*)d_in[10];
    const float* mWih = (const float*)d_in[11];
    const float* mWhh = (const float*)d_in[12];
    const float* mbih = (const float*)d_in[13];
    const float* mbhh = (const float*)d_in[14];
    const float* Wx_w = (const float*)d_in[15];
    const float* Wx_b = (const float*)d_in[16];
    const float* Wh_w = (const float*)d_in[17];
    const float* V_w  = (const float*)d_in[18];
    const float* V_b  = (const float*)d_in[19];
    const float* dWih = (const float*)d_in[20];
    const float* dWhh = (const float*)d_in[21];
    const float* dbih = (const float*)d_in[22];
    const float* dbhh = (const float*)d_in[23];
    const float* regw = (const float*)d_in[24];
    const float* regb = (const float*)d_in[25];

    k_tr<<<256, 256>>>(eWih, eWhh, mWih, mWhh, dWih, dWhh,
                       We_w, Wi_w, Vd_w, Wh_w, Wx_w);
    k_enc_mid<<<NB / 8, 512>>>(X, Wi_b, Vd_b, ebih, ebhh, mbih, mbhh);
    k_wx<<<(NB / 2 * TE) / 16, 256>>>(Wx_b);
    k_dec<<<NB / 8, 512>>>(V_w, V_b, dbih, dbhh, regw, regb, (float*)d_out);
}